// round 15
// baseline (speedup 1.0000x reference)
#include <cuda_runtime.h>
#include <cuda_bf16.h>
#include <cstdint>
#include <cstddef>

// Problem constants
#define EMB   768
#define DK    256
#define DV    256
#define BB    8
#define NN    2048
#define HH    3
#define MALL  (BB*NN)          // 16384

typedef __nv_bfloat16 bf16;
typedef long long ll;

// ---------------------------------------------------------------------------
// Scratch (device globals — allocation is forbidden)
// ---------------------------------------------------------------------------
__device__ float g_rs[HH * BB * NN * 32];          // partial row sums of exp(S)

__device__ bf16 g_xh[MALL * EMB],  g_xl[MALL * EMB];
__device__ bf16 g_Qh[HH * MALL * DK], g_Ql[HH * MALL * DK];
__device__ bf16 g_Kh[HH * MALL * DK], g_Kl[HH * MALL * DK];
__device__ bf16 g_Vth[HH * MALL * DV], g_Vtl[HH * MALL * DV];  // V^T [h][b][DV][NN]
__device__ bf16 g_Ph[(size_t)HH * BB * NN * NN], g_Pl[(size_t)HH * BB * NN * NN];
__device__ bf16 g_Ch[MALL * HH * DV], g_Cl[MALL * HH * DV];    // concat hi/lo
__device__ bf16 g_Wqt[HH * DK * EMB], g_Wqtl[HH * DK * EMB];   // W^T [h][256][768]
__device__ bf16 g_Wkt[HH * DK * EMB], g_Wktl[HH * DK * EMB];
__device__ bf16 g_Wvt[HH * DV * EMB], g_Wvtl[HH * DV * EMB];
__device__ bf16 g_W0t[EMB * EMB],     g_W0tl[EMB * EMB];       // W0^T [768][768]

// ---------------------------------------------------------------------------
// PTX helpers (sm_80-compatible only: ldmatrix / mma.sync / cp.async)
// ---------------------------------------------------------------------------
__device__ __forceinline__ uint32_t smem_to_u32(const void* p) {
    uint32_t a;
    asm("{ .reg .u64 t; cvta.to.shared.u64 t, %1; cvt.u32.u64 %0, t; }" : "=r"(a) : "l"(p));
    return a;
}
__device__ __forceinline__ void ldsm4(uint32_t& r0, uint32_t& r1, uint32_t& r2,
                                      uint32_t& r3, uint32_t addr) {
    asm volatile("ldmatrix.sync.aligned.m8n8.x4.shared.b16 {%0,%1,%2,%3}, [%4];"
                 : "=r"(r0), "=r"(r1), "=r"(r2), "=r"(r3) : "r"(addr));
}
__device__ __forceinline__ void mma_bf16(float* d, const uint32_t* a, const uint32_t* b) {
    asm volatile("mma.sync.aligned.m16n8k16.row.col.f32.bf16.bf16.f32 "
                 "{%0,%1,%2,%3}, {%4,%5,%6,%7}, {%8,%9}, {%0,%1,%2,%3};"
                 : "+f"(d[0]), "+f"(d[1]), "+f"(d[2]), "+f"(d[3])
                 : "r"(a[0]), "r"(a[1]), "r"(a[2]), "r"(a[3]), "r"(b[0]), "r"(b[1]));
}
__device__ __forceinline__ void cpasync16(uint32_t dst, const void* src) {
    asm volatile("cp.async.cg.shared.global [%0], [%1], 16;" :: "r"(dst), "l"(src));
}
#define CP_COMMIT() asm volatile("cp.async.commit_group;" ::: "memory")
#define CP_WAIT(n)  asm volatile("cp.async.wait_group %0;" :: "n"(n) : "memory")

// ---------------------------------------------------------------------------
// Warp-MMA bf16 split GEMM: acc[m,n] = sum_k A[m,k]*B[n,k]
//   3-pass split accumulation (AhBh + AhBl + AlBh), fp32 registers.
//   CTA tile 128x128, BK=32, 128 threads (4 warps, 2x2 grid, 64x64/warp),
//   3-stage cp.async (1 barrier/kt, sync-then-issue), swizzled smem, 2 CTA/SM.
//   OMODE 0: fp32 C = alpha*acc + bias.
//   OMODE 1: bf16 hi/lo (Coh/Col) = alpha*acc + bias, row-major ldc.
//   OMODE 2: bf16 hi/lo TRANSPOSED per batch: out[(m>>11)*DV + n][NN] + (m&2047)
//   OMODE 3: P = exp(alpha*acc) -> bf16 hi/lo + partial row sums to rs (bias ptr)
//   OMODE 4: bf16 hi/lo = acc / rowsum(rs[row])  (rs via bias ptr)
// ---------------------------------------------------------------------------
// smem: rows of 64B (no pad), 16B-chunk swizzle: sc = c ^ ((row>>1)&3)
#define TILEB  8192                // 128 rows x 64 B
#define STAGEB (4 * TILEB)         // 32768: Ah, Al, Bh, Bl
#define NSTG   3
#define GSM    (NSTG * STAGEB)     // 98304 -> 2 CTAs/SM

template<int OMODE>
__global__ __launch_bounds__(128, 2)
void gemm_mma(const bf16* __restrict__ Ah, const bf16* __restrict__ Al,
              ll sA1, ll sA2,
              const bf16* __restrict__ Bh, const bf16* __restrict__ Bl,
              ll sB1, ll sB2,
              const float* __restrict__ bias, ll sb1, ll sb2,
              float* __restrict__ C, bf16* __restrict__ Coh, bf16* __restrict__ Col,
              int ldc, ll sC1, ll sC2,
              int Kdim, float alpha, int Z2)
{
    const int z  = blockIdx.z;
    const int z1 = z / Z2;
    const int z2 = z - z1 * Z2;
    Ah += z1 * sA1 + z2 * sA2;  Al += z1 * sA1 + z2 * sA2;
    Bh += z1 * sB1 + z2 * sB2;  Bl += z1 * sB1 + z2 * sB2;
    if (OMODE == 0) C += z1 * sC1 + z2 * sC2;
    else { Coh += z1 * sC1 + z2 * sC2; Col += z1 * sC1 + z2 * sC2; }
    const float* bptr = bias ? bias + z1 * sb1 + z2 * sb2 : nullptr;

    const int m0 = blockIdx.y * 128;
    const int n0 = blockIdx.x * 128;

    extern __shared__ char smem[];
    const uint32_t sb = smem_to_u32(smem);
    const int tid  = threadIdx.x;
    const int wid  = tid >> 5;            // 0..3 (4 warps)
    const int lane = tid & 31;
    const int wm   = wid >> 1;            // 0..1 (64-row band)
    const int wn   = wid & 1;             // 0..1 (64-col band)

    // ---- loader: 128 threads, 16 x 16B chunks each (4 per tile) ----
    const int lr  = tid >> 2;             // 0..31 base row
    const int lc  = tid & 3;              // 16B chunk in 64B row
    const int scw = lc ^ ((lr >> 1) & 3); // swizzled chunk (row step 32 keeps it)
    const int KT  = Kdim >> 5;

    auto issue_loads = [&](int kt, int stage) {
        const uint32_t sbase = sb + stage * STAGEB + (uint32_t)(lr * 64 + scw * 16);
        const int koff = (kt << 5) + lc * 8;
        const size_t step = (size_t)32 * Kdim;
        const bf16* pAh = Ah + (size_t)(m0 + lr) * Kdim + koff;
        const bf16* pAl = Al + (size_t)(m0 + lr) * Kdim + koff;
        const bf16* pBh = Bh + (size_t)(n0 + lr) * Kdim + koff;
        const bf16* pBl = Bl + (size_t)(n0 + lr) * Kdim + koff;
#pragma unroll
        for (int j = 0; j < 4; j++) cpasync16(sbase + j * 2048, pAh + j * step);
#pragma unroll
        for (int j = 0; j < 4; j++) cpasync16(sbase + TILEB + j * 2048, pAl + j * step);
#pragma unroll
        for (int j = 0; j < 4; j++) cpasync16(sbase + 2 * TILEB + j * 2048, pBh + j * step);
#pragma unroll
        for (int j = 0; j < 4; j++) cpasync16(sbase + 3 * TILEB + j * 2048, pBl + j * step);
        CP_COMMIT();
    };

    const int l15 = lane & 15;
    const int lsw = (l15 >> 1) & 3;
    const uint32_t swk[2] = {
        (uint32_t)((((lane >> 4) + 0) ^ lsw) * 16),
        (uint32_t)((((lane >> 4) + 2) ^ lsw) * 16)
    };

    float acc[4][8][4];
#pragma unroll
    for (int i = 0; i < 4; i++)
#pragma unroll
        for (int j = 0; j < 8; j++)
#pragma unroll
            for (int q = 0; q < 4; q++) acc[i][j][q] = 0.f;

    issue_loads(0, 0);
    issue_loads(1, 1);

    int s = 0, s2 = 2;
    for (int kt = 0; kt < KT; kt++) {
        if (kt + 1 < KT) { CP_WAIT(1); } else { CP_WAIT(0); }
        __syncthreads();
        if (kt + 2 < KT) issue_loads(kt + 2, s2);   // stage all warps just freed

        const uint32_t base = sb + s * STAGEB;
#pragma unroll
        for (int ks = 0; ks < 2; ks++) {
            const uint32_t arow = base + (uint32_t)((wm * 64 + l15) * 64) + swk[ks];
            const uint32_t brow = base + 2 * TILEB
                                + (uint32_t)((wn * 64 + l15) * 64) + swk[ks];

            uint32_t bh[8][2], bl[8][2];
#pragma unroll
            for (int g = 0; g < 4; g++) {
                uint32_t r0, r1, r2, r3;
                ldsm4(r0, r1, r2, r3, brow + g * 16 * 64);
                bh[g * 2 + 0][0] = r0; bh[g * 2 + 0][1] = r2;
                bh[g * 2 + 1][0] = r1; bh[g * 2 + 1][1] = r3;
                ldsm4(r0, r1, r2, r3, brow + TILEB + g * 16 * 64);
                bl[g * 2 + 0][0] = r0; bl[g * 2 + 0][1] = r2;
                bl[g * 2 + 1][0] = r1; bl[g * 2 + 1][1] = r3;
            }
#pragma unroll
            for (int mt = 0; mt < 4; mt++) {
                uint32_t ah[4], al[4];
                ldsm4(ah[0], ah[1], ah[2], ah[3], arow + mt * 16 * 64);
                ldsm4(al[0], al[1], al[2], al[3], arow + TILEB + mt * 16 * 64);
#pragma unroll
                for (int nt = 0; nt < 8; nt++) {
                    mma_bf16(acc[mt][nt], ah, bh[nt]);
                    mma_bf16(acc[mt][nt], ah, bl[nt]);
                    mma_bf16(acc[mt][nt], al, bh[nt]);
                }
            }
        }
        s  = (s  == 2) ? 0 : s  + 1;
        s2 = (s2 == 2) ? 0 : s2 + 1;
    }

    // =========================== epilogues ===========================
    if (OMODE == 3) {
        // exp + P hi/lo + partial row sums (64-col strip = blockIdx.x*2 + wn)
        float* rsw = (float*)bptr;
#pragma unroll
        for (int mt = 0; mt < 4; mt++)
#pragma unroll
            for (int h = 0; h < 2; h++) {
                const int row = m0 + wm * 64 + mt * 16 + h * 8 + (lane >> 2);
                float s8 = 0.f;
#pragma unroll
                for (int nt = 0; nt < 8; nt++) {
                    const float e0 = __expf(acc[mt][nt][2 * h + 0] * alpha);
                    const float e1 = __expf(acc[mt][nt][2 * h + 1] * alpha);
                    s8 += e0 + e1;
                    const int col = n0 + wn * 64 + nt * 8 + (lane & 3) * 2;
                    const size_t off = (size_t)row * ldc + col;
                    const bf16 h0 = __float2bfloat16(e0);
                    const bf16 h1 = __float2bfloat16(e1);
                    *(__nv_bfloat162*)(Coh + off) = __nv_bfloat162(h0, h1);
                    *(__nv_bfloat162*)(Col + off) = __nv_bfloat162(
                        __float2bfloat16(e0 - __bfloat162float(h0)),
                        __float2bfloat16(e1 - __bfloat162float(h1)));
                }
                s8 += __shfl_xor_sync(0xffffffffu, s8, 1);
                s8 += __shfl_xor_sync(0xffffffffu, s8, 2);
                if ((lane & 3) == 0)
                    rsw[(size_t)row * 32 + blockIdx.x * 2 + wn] = s8;
            }
        return;
    }

    float* sinv = (float*)smem;
    if (OMODE == 4) {
        // cooperative rowsum: 128 rows, 32 partials each (1 row/thread)
        __syncthreads();
        {
            const float4* p4 = (const float4*)(bptr + (size_t)(m0 + tid) * 32);
            float ssum = 0.f;
#pragma unroll
            for (int i = 0; i < 8; i++) {
                const float4 v = p4[i];
                ssum += v.x + v.y + v.z + v.w;
            }
            sinv[tid] = 1.0f / ssum;
        }
        __syncthreads();
    }

#pragma unroll
    for (int mt = 0; mt < 4; mt++)
#pragma unroll
        for (int nt = 0; nt < 8; nt++) {
            const int row0 = m0 + wm * 64 + mt * 16 + (lane >> 2);
            const int col  = n0 + wn * 64 + nt * 8 + (lane & 3) * 2;
            float b0v = 0.f, b1v = 0.f;
            if (bptr && OMODE <= 2) { b0v = __ldg(bptr + col); b1v = __ldg(bptr + col + 1); }
#pragma unroll
            for (int h = 0; h < 2; h++) {
                const int row = row0 + 8 * h;
                float sc = alpha;
                if (OMODE == 4) sc = sinv[row - m0];
                const float v0 = acc[mt][nt][2 * h + 0] * sc + b0v;
                const float v1 = acc[mt][nt][2 * h + 1] * sc + b1v;
                if (OMODE == 0) {
                    *(float2*)(C + (size_t)row * ldc + col) = make_float2(v0, v1);
                } else if (OMODE == 1 || OMODE == 4) {
                    const size_t off = (size_t)row * ldc + col;
                    const bf16 h0 = __float2bfloat16(v0);
                    const bf16 h1 = __float2bfloat16(v1);
                    *(__nv_bfloat162*)(Coh + off) = __nv_bfloat162(h0, h1);
                    *(__nv_bfloat162*)(Col + off) = __nv_bfloat162(
                        __float2bfloat16(v0 - __bfloat162float(h0)),
                        __float2bfloat16(v1 - __bfloat162float(h1)));
                } else {
                    const ll off = ((ll)(row >> 11) * DV + col) * NN + (row & (NN - 1));
                    const bf16 h0 = __float2bfloat16(v0);
                    const bf16 h1 = __float2bfloat16(v1);
                    Coh[off]      = h0;
                    Coh[off + NN] = h1;
                    Col[off]      = __float2bfloat16(v0 - __bfloat162float(h0));
                    Col[off + NN] = __float2bfloat16(v1 - __bfloat162float(h1));
                }
            }
        }
}

// ---------------------------------------------------------------------------
// fp32 -> (hi, lo) bf16 split, elementwise
// ---------------------------------------------------------------------------
__global__ void split4(const float* __restrict__ in, bf16* __restrict__ oh,
                       bf16* __restrict__ ol, int n4)
{
    const int i = blockIdx.x * blockDim.x + threadIdx.x;
    if (i >= n4) return;
    const float4 v = ((const float4*)in)[i];
    bf16 h0 = __float2bfloat16(v.x), h1 = __float2bfloat16(v.y);
    bf16 h2 = __float2bfloat16(v.z), h3 = __float2bfloat16(v.w);
    bf16 l0 = __float2bfloat16(v.x - __bfloat162float(h0));
    bf16 l1 = __float2bfloat16(v.y - __bfloat162float(h1));
    bf16 l2 = __float2bfloat16(v.z - __bfloat162float(h2));
    bf16 l3 = __float2bfloat16(v.w - __bfloat162float(h3));
    ((__nv_bfloat162*)oh)[2 * i + 0] = __nv_bfloat162(h0, h1);
    ((__nv_bfloat162*)oh)[2 * i + 1] = __nv_bfloat162(h2, h3);
    ((__nv_bfloat162*)ol)[2 * i + 0] = __nv_bfloat162(l0, l1);
    ((__nv_bfloat162*)ol)[2 * i + 1] = __nv_bfloat162(l2, l3);
}

// ---------------------------------------------------------------------------
// Batched transpose + split (weights only): in[R][Cc] fp32 -> out hi/lo [Cc][R]
// ---------------------------------------------------------------------------
__global__ void transpose_split(const float* __restrict__ in, bf16* __restrict__ oh,
                                bf16* __restrict__ ol, int R, int Cc,
                                ll sIn, ll sOut)
{
    __shared__ float tle[32][33];
    const int z = blockIdx.z;
    in += z * sIn;  oh += z * sOut;  ol += z * sOut;
    const int c0 = blockIdx.x * 32, r0 = blockIdx.y * 32;
    const int x = threadIdx.x, y = threadIdx.y;
#pragma unroll
    for (int i = 0; i < 32; i += 8)
        tle[y + i][x] = in[(size_t)(r0 + y + i) * Cc + c0 + x];
    __syncthreads();
#pragma unroll
    for (int i = 0; i < 32; i += 8) {
        const float v = tle[x][y + i];
        const bf16 h = __float2bfloat16(v);
        const size_t o = (size_t)(c0 + y + i) * R + r0 + x;
        oh[o] = h;
        ol[o] = __float2bfloat16(v - __bfloat162float(h));
    }
}

// ---------------------------------------------------------------------------
// Launch
// ---------------------------------------------------------------------------
extern "C" void kernel_launch(void* const* d_in, const int* in_sizes, int n_in,
                              void* d_out, int out_size)
{
    const float* x  = (const float*)d_in[0];
    const float* Wq = (const float*)d_in[1];
    const float* bq = (const float*)d_in[2];
    const float* Wk = (const float*)d_in[3];
    const float* bk = (const float*)d_in[4];
    const float* Wv = (const float*)d_in[5];
    const float* bv = (const float*)d_in[6];
    const float* W0 = (const float*)d_in[7];
    const float* b0 = (const float*)d_in[8];
    float* out = (float*)d_out;

    float *rs;
    bf16 *xh, *xl, *Qh, *Ql, *Kh, *Kl, *Vth, *Vtl, *Ph, *Pl, *Ch, *Cl;
    bf16 *Wqt, *Wqtl, *Wkt, *Wktl, *Wvt, *Wvtl, *W0t, *W0tl;
    cudaGetSymbolAddress((void**)&rs, g_rs);
    cudaGetSymbolAddress((void**)&xh, g_xh);  cudaGetSymbolAddress((void**)&xl, g_xl);
    cudaGetSymbolAddress((void**)&Qh, g_Qh);  cudaGetSymbolAddress((void**)&Ql, g_Ql);
    cudaGetSymbolAddress((void**)&Kh, g_Kh);  cudaGetSymbolAddress((void**)&Kl, g_Kl);
    cudaGetSymbolAddress((void**)&Vth, g_Vth);cudaGetSymbolAddress((void**)&Vtl, g_Vtl);
    cudaGetSymbolAddress((void**)&Ph, g_Ph);  cudaGetSymbolAddress((void**)&Pl, g_Pl);
    cudaGetSymbolAddress((void**)&Ch, g_Ch);  cudaGetSymbolAddress((void**)&Cl, g_Cl);
    cudaGetSymbolAddress((void**)&Wqt, g_Wqt);   cudaGetSymbolAddress((void**)&Wqtl, g_Wqtl);
    cudaGetSymbolAddress((void**)&Wkt, g_Wkt);   cudaGetSymbolAddress((void**)&Wktl, g_Wktl);
    cudaGetSymbolAddress((void**)&Wvt, g_Wvt);   cudaGetSymbolAddress((void**)&Wvtl, g_Wvtl);
    cudaGetSymbolAddress((void**)&W0t, g_W0t);   cudaGetSymbolAddress((void**)&W0tl, g_W0tl);

    cudaFuncSetAttribute(gemm_mma<0>, cudaFuncAttributeMaxDynamicSharedMemorySize, GSM);
    cudaFuncSetAttribute(gemm_mma<1>, cudaFuncAttributeMaxDynamicSharedMemorySize, GSM);
    cudaFuncSetAttribute(gemm_mma<2>, cudaFuncAttributeMaxDynamicSharedMemorySize, GSM);
    cudaFuncSetAttribute(gemm_mma<3>, cudaFuncAttributeMaxDynamicSharedMemorySize, GSM);
    cudaFuncSetAttribute(gemm_mma<4>, cudaFuncAttributeMaxDynamicSharedMemorySize, GSM);

    const dim3 tb(32, 8);

    // --- operand prep ---
    split4<<<(MALL * EMB / 4 + 255) / 256, 256>>>(x, xh, xl, MALL * EMB / 4);
    transpose_split<<<dim3(8, 24, 3), tb>>>(Wq, Wqt, Wqtl, EMB, DK,
                                            (ll)EMB * DK, (ll)EMB * DK);
    transpose_split<<<dim3(8, 24, 3), tb>>>(Wk, Wkt, Wktl, EMB, DK,
                                            (ll)EMB * DK, (ll)EMB * DK);
    transpose_split<<<dim3(8, 24, 3), tb>>>(Wv, Wvt, Wvtl, EMB, DV,
                                            (ll)EMB * DV, (ll)EMB * DV);
    transpose_split<<<dim3(24, 24, 1), tb>>>(W0, W0t, W0tl, EMB, EMB, 0, 0);

    // --- QKV projections: [16384,768] x [256,768]^T, batched over 3 heads ---
    {
        const dim3 g(DK / 128, MALL / 128, HH);
        gemm_mma<1><<<g, 128, GSM>>>(xh, xl, 0, 0,
                                     Wqt, Wqtl, 0, (ll)DK * EMB,
                                     bq, 0, DK,
                                     nullptr, Qh, Ql, DK, 0, (ll)MALL * DK,
                                     EMB, 1.0f, HH);
        gemm_mma<1><<<g, 128, GSM>>>(xh, xl, 0, 0,
                                     Wkt, Wktl, 0, (ll)DK * EMB,
                                     bk, 0, DK,
                                     nullptr, Kh, Kl, DK, 0, (ll)MALL * DK,
                                     EMB, 1.0f, HH);
        gemm_mma<2><<<g, 128, GSM>>>(xh, xl, 0, 0,
                                     Wvt, Wvtl, 0, (ll)DV * EMB,
                                     bv, 0, DV,
                                     nullptr, Vth, Vtl, 0, 0, (ll)BB * DV * NN,
                                     EMB, 1.0f, HH);
    }

    // --- scores+exp: P = exp(Q K^T / 16) hi/lo + partial row sums, 24 batches ---
    gemm_mma<3><<<dim3(NN / 128, NN / 128, HH * BB), 128, GSM>>>(
        Qh, Ql, (ll)MALL * DK, (ll)NN * DK,
        Kh, Kl, (ll)MALL * DK, (ll)NN * DK,
        rs, (ll)BB * NN * 32, (ll)NN * 32,
        nullptr, Ph, Pl, NN, (ll)BB * NN * NN, (ll)NN * NN,
        DK, 0.0625f, BB);

    // --- PV: O = (P V) / rowsum into concat layout, bf16 hi/lo out ---
    gemm_mma<4><<<dim3(DV / 128, NN / 128, HH * BB), 128, GSM>>>(
        Ph, Pl, (ll)BB * NN * NN, (ll)NN * NN,
        Vth, Vtl, (ll)BB * DV * NN, (ll)DV * NN,
        rs, (ll)BB * NN * 32, (ll)NN * 32,
        nullptr, Ch, Cl, HH * DV, DV, (ll)NN * (HH * DV),
        NN, 1.0f, BB);

    // --- output projection: [16384,768] x [768,768]^T + b0 ---
    gemm_mma<0><<<dim3(EMB / 128, MALL / 128, 1), 128, GSM>>>(
        Ch, Cl, 0, 0,
        W0t, W0tl, 0, 0,
        b0, 0, 0,
        out, nullptr, nullptr, EMB, 0, 0,
        HH * DV, 1.0f, 1);
}